// round 8
// baseline (speedup 1.0000x reference)
#include <cuda_runtime.h>
#include <cstdint>

#define N_NODES 50000
#define NPAD    50048   // 128*391
#define NE      800000
#define HD      64
#define TSTEPS  4
#define RSTRIDE 132     // muT row stride in floats

// ---------- device scratch ----------
__device__ float    g_deg[N_NODES];
__device__ float    g_sw[N_NODES];
__device__ float    g_c3[TSTEPS * HD];
__device__ float    g_S[HD];
__device__ uint64_t g_WT2[5][HD][HD];   // splatted transposed weights: (w,w) pairs
__device__ float    g_muT[HD][NPAD];    // transposed mu

// ---------- f32x2 helpers ----------
__device__ __forceinline__ void ffma2(uint64_t& acc, uint64_t a, uint64_t b) {
    asm("fma.rn.f32x2 %0, %1, %2, %0;" : "+l"(acc) : "l"(a), "l"(b));
}
__device__ __forceinline__ uint64_t pack2(float lo, float hi) {
    uint64_t r;
    asm("mov.b64 %0, {%1, %2};" : "=l"(r) : "f"(lo), "f"(hi));
    return r;
}
__device__ __forceinline__ float2 unpack2(uint64_t v) {
    float lo, hi;
    asm("mov.b64 {%0, %1}, %2;" : "=f"(lo), "=f"(hi) : "l"(v));
    return make_float2(lo, hi);
}
__device__ __forceinline__ uint32_t sptr(const void* p) {
    uint32_t r;
    asm("{.reg .u64 t; cvta.to.shared.u64 t, %1; cvt.u32.u64 %0, t;}"
        : "=r"(r) : "l"(p));
    return r;
}
__device__ __forceinline__ void lds_v2u64(uint64_t& a, uint64_t& b, uint32_t off) {
    asm("ld.shared.v2.u64 {%0, %1}, [%2];" : "=l"(a), "=l"(b) : "r"(off));
}

// ---------- prep kernel: zero + c3 + transW(splat) + transMu, one launch ----------
__global__ void __launch_bounds__(256)
prep_kernel(const float* __restrict__ mu, const float* __restrict__ W2,
            const float* __restrict__ W7, const float* __restrict__ W3,
            const float* __restrict__ W4) {
    __shared__ float S[64][65];
    int b = blockIdx.x;
    int tid = threadIdx.x;

    if (b < 782) {                       // transMu (64-row tiles)
        int v0 = b * 64;
#pragma unroll
        for (int s = 0; s < 16; s++) {
            int j = tid + 256 * s;
            int r = j >> 6, k = j & 63;
            int v = v0 + r;
            S[r][k] = (v < N_NODES) ? mu[v * 64 + k] : 0.f;
        }
        __syncthreads();
#pragma unroll
        for (int s = 0; s < 16; s++) {
            int j = tid + 256 * s;
            int k = j >> 6, r = j & 63;
            g_muT[k][v0 + r] = S[r][k];
        }
    } else if (b < 978) {                // zero deg/sw
        int i = (b - 782) * 256 + tid;
        if (i < N_NODES) { g_deg[i] = 0.f; g_sw[i] = 0.f; }
    } else if (b == 978) {               // c3 + zero g_S
        int t = tid >> 6, h = tid & 63;
        S[t][h] = fmaxf(W4[t * HD + h], 0.f);
        if (tid < 64) g_S[tid] = 0.f;
        __syncthreads();
        float s = 0.f;
        const float* row = W3 + t * HD * HD + h * HD;
#pragma unroll 16
        for (int k = 0; k < HD; k++) s = fmaf(row[k], S[t][k], s);
        g_c3[t * HD + h] = s;
    } else {                             // transW + splat
        int l = b - 979;
        const float* src = (l < 4) ? (W2 + l * 4096) : W7;
#pragma unroll
        for (int s = 0; s < 16; s++) {
            int j = tid + 256 * s;
            S[j >> 6][j & 63] = src[j];
        }
        __syncthreads();
#pragma unroll
        for (int s = 0; s < 16; s++) {
            int j = tid + 256 * s;
            float w = S[j & 63][j >> 6];     // WT[k][h] = W[h][k]
            g_WT2[l][j >> 6][j & 63] = pack2(w, w);
        }
    }
}

// ---------- edge kernel: 4 edges/thread ----------
__global__ void edge_kernel(const int* __restrict__ ei,
                            const float* __restrict__ ew) {
    int t4 = blockIdx.x * blockDim.x + threadIdx.x;
    if (t4 < NE / 4) {
        int4   v4 = *(const int4*)(ei + NE + 4 * t4);
        float4 w4 = *(const float4*)(ew + 4 * t4);
        if ((unsigned)v4.x < N_NODES) { atomicAdd(&g_deg[v4.x], 1.0f); atomicAdd(&g_sw[v4.x], w4.x); }
        if ((unsigned)v4.y < N_NODES) { atomicAdd(&g_deg[v4.y], 1.0f); atomicAdd(&g_sw[v4.y], w4.y); }
        if ((unsigned)v4.z < N_NODES) { atomicAdd(&g_deg[v4.z], 1.0f); atomicAdd(&g_sw[v4.z], w4.z); }
        if ((unsigned)v4.w < N_NODES) { atomicAdd(&g_deg[v4.w], 1.0f); atomicAdd(&g_sw[v4.w], w4.w); }
    }
}

// ---------- fused kernel: 4 S2V steps + readout; 128-node tile, 256 threads ----------
// Thread tile: 4 cols (c0=4*(tid>>4)) x 8 rows ({4qy..+3} U {64+4qy..+3}).
// Weights pre-splatted as u64 pairs -> mainloop = 4 LDS + 16 FFMA2 per k.
__global__ void __launch_bounds__(256)
fused_kernel(const float* __restrict__ x,
             const float* __restrict__ W1,
             const float* __restrict__ W5,
             float* __restrict__ out) {
    __shared__ __align__(16) uint64_t Ws2[HD][HD];      // splatted weights [k][h]
    __shared__ __align__(16) float muT[HD][RSTRIDE];    // [k][row 0..127]
    __shared__ float xs[128], degs[128], sws[128];
    __shared__ float w1s[64], c3s[64];
    __shared__ float colp[4][64];

    float (*red)[17] = (float (*)[17])&muT[0][0];       // alias (muT dead at use)

    const int tid = threadIdx.x;
    const int cx = tid >> 4;       // 0..15
    const int qy = tid & 15;       // 0..15
    const int c0 = cx * 4;
    const int rA = qy * 4;
    const int rB = 64 + qy * 4;
    const int v0 = blockIdx.x * 128;

    const uint32_t ws2_base = sptr(&Ws2[0][0]) + c0 * 8;

    // stage mu tile: straight float4 copies
#pragma unroll
    for (int s = 0; s < 8; s++) {
        int j = tid + 256 * s;
        int k = j >> 5, q = j & 31;
        *(float4*)&muT[k][4 * q] = *(const float4*)&g_muT[k][v0 + 4 * q];
    }
    if (tid < 128) {
        int v = v0 + tid;
        xs[tid]   = (v < N_NODES) ? x[v]     : 0.f;
        degs[tid] = (v < N_NODES) ? g_deg[v] : 0.f;
        sws[tid]  = (v < N_NODES) ? g_sw[v]  : 0.f;
    }

#pragma unroll 1
    for (int t = 0; t < TSTEPS; t++) {
        __syncthreads();
        // stage splatted weights: 4096 u64 = 2048 float4
#pragma unroll
        for (int s = 0; s < 8; s++) {
            int j = tid + 256 * s;
            int k = j >> 5, q = j & 31;
            *(float4*)((char*)&Ws2[k][0] + 16 * q) =
                *(const float4*)((const char*)&g_WT2[t][k][0] + 16 * q);
        }
        if (tid < 64) { w1s[tid] = W1[t * 64 + tid]; c3s[tid] = g_c3[t * 64 + tid]; }
        __syncthreads();

        uint64_t acc[4][4];   // [col i][pair: rA01,rA23,rB01,rB23]
#pragma unroll
        for (int i = 0; i < 4; i++)
#pragma unroll
            for (int p = 0; p < 4; p++) acc[i][p] = 0ULL;

        uint32_t woff = ws2_base;
#pragma unroll 8
        for (int k = 0; k < 64; k++) {
            uint64_t w0, w1, w2, w3;
            lds_v2u64(w0, w1, woff);
            lds_v2u64(w2, w3, woff + 16);
            woff += HD * 8;
            float4 mA = *(const float4*)&muT[k][rA];
            float4 mB = *(const float4*)&muT[k][rB];
            uint64_t a01 = pack2(mA.x, mA.y), a23 = pack2(mA.z, mA.w);
            uint64_t b01 = pack2(mB.x, mB.y), b23 = pack2(mB.z, mB.w);
            ffma2(acc[0][0], a01, w0); ffma2(acc[0][1], a23, w0);
            ffma2(acc[0][2], b01, w0); ffma2(acc[0][3], b23, w0);
            ffma2(acc[1][0], a01, w1); ffma2(acc[1][1], a23, w1);
            ffma2(acc[1][2], b01, w1); ffma2(acc[1][3], b23, w1);
            ffma2(acc[2][0], a01, w2); ffma2(acc[2][1], a23, w2);
            ffma2(acc[2][2], b01, w2); ffma2(acc[2][3], b23, w2);
            ffma2(acc[3][0], a01, w3); ffma2(acc[3][1], a23, w3);
            ffma2(acc[3][2], b01, w3); ffma2(acc[3][3], b23, w3);
        }
        __syncthreads();

        // epilogue: mu' = relu(x*w1 + deg*acc + sw*c3)
#pragma unroll
        for (int i = 0; i < 4; i++) {
            int c = c0 + i;
            float w1c = w1s[c], c3c = c3s[c];
            float2 p0 = unpack2(acc[i][0]);
            float2 p1 = unpack2(acc[i][1]);
            float4 o;
            o.x = fmaxf(fmaf(xs[rA+0], w1c, fmaf(degs[rA+0], p0.x, sws[rA+0] * c3c)), 0.f);
            o.y = fmaxf(fmaf(xs[rA+1], w1c, fmaf(degs[rA+1], p0.y, sws[rA+1] * c3c)), 0.f);
            o.z = fmaxf(fmaf(xs[rA+2], w1c, fmaf(degs[rA+2], p1.x, sws[rA+2] * c3c)), 0.f);
            o.w = fmaxf(fmaf(xs[rA+3], w1c, fmaf(degs[rA+3], p1.y, sws[rA+3] * c3c)), 0.f);
            *(float4*)&muT[c][rA] = o;
            float2 p2 = unpack2(acc[i][2]);
            float2 p3 = unpack2(acc[i][3]);
            o.x = fmaxf(fmaf(xs[rB+0], w1c, fmaf(degs[rB+0], p2.x, sws[rB+0] * c3c)), 0.f);
            o.y = fmaxf(fmaf(xs[rB+1], w1c, fmaf(degs[rB+1], p2.y, sws[rB+1] * c3c)), 0.f);
            o.z = fmaxf(fmaf(xs[rB+2], w1c, fmaf(degs[rB+2], p3.x, sws[rB+2] * c3c)), 0.f);
            o.w = fmaxf(fmaf(xs[rB+3], w1c, fmaf(degs[rB+3], p3.y, sws[rB+3] * c3c)), 0.f);
            *(float4*)&muT[c][rB] = o;
        }
    }
    __syncthreads();

    // graph-pool column partials over 128 rows
    {
        int h = tid & 63, g = tid >> 6;
        float s = 0.f;
#pragma unroll
        for (int j = 0; j < 32; j++) s += muT[h][g * 32 + j];
        colp[g][h] = s;
    }
    // stage W7^T (splatted) and W5 node-half
#pragma unroll
    for (int s = 0; s < 8; s++) {
        int j = tid + 256 * s;
        int k = j >> 5, q = j & 31;
        *(float4*)((char*)&Ws2[k][0] + 16 * q) =
            *(const float4*)((const char*)&g_WT2[4][k][0] + 16 * q);
    }
    if (tid < 64) w1s[tid] = W5[64 + tid];
    __syncthreads();

    if (tid < 64)
        atomicAdd(&g_S[tid], colp[0][tid] + colp[1][tid] + colp[2][tid] + colp[3][tid]);

    // final GEMM: nodes_vec = mu @ W7^T
    uint64_t acc[4][4];
#pragma unroll
    for (int i = 0; i < 4; i++)
#pragma unroll
        for (int p = 0; p < 4; p++) acc[i][p] = 0ULL;

    uint32_t woff = ws2_base;
#pragma unroll 8
    for (int k = 0; k < 64; k++) {
        uint64_t w0, w1, w2, w3;
        lds_v2u64(w0, w1, woff);
        lds_v2u64(w2, w3, woff + 16);
        woff += HD * 8;
        float4 mA = *(const float4*)&muT[k][rA];
        float4 mB = *(const float4*)&muT[k][rB];
        uint64_t a01 = pack2(mA.x, mA.y), a23 = pack2(mA.z, mA.w);
        uint64_t b01 = pack2(mB.x, mB.y), b23 = pack2(mB.z, mB.w);
        ffma2(acc[0][0], a01, w0); ffma2(acc[0][1], a23, w0);
        ffma2(acc[0][2], b01, w0); ffma2(acc[0][3], b23, w0);
        ffma2(acc[1][0], a01, w1); ffma2(acc[1][1], a23, w1);
        ffma2(acc[1][2], b01, w1); ffma2(acc[1][3], b23, w1);
        ffma2(acc[2][0], a01, w2); ffma2(acc[2][1], a23, w2);
        ffma2(acc[2][2], b01, w2); ffma2(acc[2][3], b23, w2);
        ffma2(acc[3][0], a01, w3); ffma2(acc[3][1], a23, w3);
        ffma2(acc[3][2], b01, w3); ffma2(acc[3][3], b23, w3);
    }

    float prA[4] = {0.f, 0.f, 0.f, 0.f};
    float prB[4] = {0.f, 0.f, 0.f, 0.f};
#pragma unroll
    for (int i = 0; i < 4; i++) {
        float wb = w1s[c0 + i];
        float2 p0 = unpack2(acc[i][0]);
        float2 p1 = unpack2(acc[i][1]);
        float2 p2 = unpack2(acc[i][2]);
        float2 p3 = unpack2(acc[i][3]);
        prA[0] = fmaf(fmaxf(p0.x, 0.f), wb, prA[0]);
        prA[1] = fmaf(fmaxf(p0.y, 0.f), wb, prA[1]);
        prA[2] = fmaf(fmaxf(p1.x, 0.f), wb, prA[2]);
        prA[3] = fmaf(fmaxf(p1.y, 0.f), wb, prA[3]);
        prB[0] = fmaf(fmaxf(p2.x, 0.f), wb, prB[0]);
        prB[1] = fmaf(fmaxf(p2.y, 0.f), wb, prB[1]);
        prB[2] = fmaf(fmaxf(p3.x, 0.f), wb, prB[2]);
        prB[3] = fmaf(fmaxf(p3.y, 0.f), wb, prB[3]);
    }
    __syncthreads();
#pragma unroll
    for (int j = 0; j < 4; j++) {
        red[rA + j][cx] = prA[j];
        red[rB + j][cx] = prB[j];
    }
    __syncthreads();

    if (tid < 128) {
        float s = 0.f;
#pragma unroll
        for (int q = 0; q < 16; q++) s += red[tid][q];
        int v = v0 + tid;
        if (v < N_NODES) out[v] = s;
    }
}

// graph-pool scalar + broadcast add (float4, N_NODES % 4 == 0)
__global__ void add_kernel(const float* __restrict__ W5, float* __restrict__ out) {
    __shared__ float sh[64];
    __shared__ float cval;
    int tid = threadIdx.x;
    if (tid < 64) sh[tid] = fmaxf(g_S[tid], 0.f) * W5[tid];
    __syncthreads();
    if (tid == 0) {
        float s = 0.f;
#pragma unroll
        for (int i = 0; i < 64; i++) s += sh[i];
        cval = s;
    }
    __syncthreads();
    int i4 = blockIdx.x * blockDim.x + tid;
    if (i4 < N_NODES / 4) {
        float4 o = *(float4*)(out + 4 * i4);
        float c = cval;
        o.x += c; o.y += c; o.z += c; o.w += c;
        *(float4*)(out + 4 * i4) = o;
    }
}

// ---------- launch ----------
extern "C" void kernel_launch(void* const* d_in, const int* in_sizes, int n_in,
                              void* d_out, int out_size) {
    const float* mu = (const float*)d_in[0];
    const float* x  = (const float*)d_in[1];
    const int*   ei = (const int*)d_in[2];     // int32 (JAX x64 disabled)
    const float* ew = (const float*)d_in[3];
    const float* W1 = (const float*)d_in[4];
    const float* W2 = (const float*)d_in[5];
    const float* W3 = (const float*)d_in[6];
    const float* W4 = (const float*)d_in[7];
    const float* W5 = (const float*)d_in[8];
    const float* W7 = (const float*)d_in[9];
    float* out = (float*)d_out;

    prep_kernel<<<984, 256>>>(mu, W2, W7, W3, W4);
    edge_kernel<<<(NE / 4 + 255) / 256, 256>>>(ei, ew);
    fused_kernel<<<NPAD / 128, 256>>>(x, W1, W5, out);
    add_kernel<<<(N_NODES / 4 + 255) / 256, 256>>>(W5, out);
}

// round 9
// speedup vs baseline: 1.0872x; 1.0872x over previous
#include <cuda_runtime.h>
#include <cstdint>

#define N_NODES 50000
#define NPAD    50048   // 128*391
#define NE      800000
#define HD      64
#define TSTEPS  4
#define RSTRIDE 132     // muT row stride in floats (33 16B-slots, odd)
#define WSTRIDE 68      // Ws row stride in floats

// ---------- device scratch ----------
__device__ float g_deg[N_NODES];
__device__ float g_sw[N_NODES];
__device__ float g_c3[TSTEPS * HD];
__device__ float g_S[HD];
__device__ float g_WT[5][HD][HD];      // [0..3]=W2[t]^T, [4]=W7^T
__device__ float g_muT[HD][NPAD];      // transposed mu

// ---------- f32x2 helpers ----------
__device__ __forceinline__ void ffma2(uint64_t& acc, uint64_t a, uint64_t b) {
    asm("fma.rn.f32x2 %0, %1, %2, %0;" : "+l"(acc) : "l"(a), "l"(b));
}
__device__ __forceinline__ uint64_t splat2(float v) {
    uint64_t r;
    asm("mov.b64 %0, {%1, %1};" : "=l"(r) : "f"(v));
    return r;
}
__device__ __forceinline__ float2 unpack2(uint64_t v) {
    float lo, hi;
    asm("mov.b64 {%0, %1}, %2;" : "=f"(lo), "=f"(hi) : "l"(v));
    return make_float2(lo, hi);
}
__device__ __forceinline__ uint32_t sptr(const void* p) {
    uint32_t r;
    asm("{.reg .u64 t; cvta.to.shared.u64 t, %1; cvt.u32.u64 %0, t;}"
        : "=r"(r) : "l"(p));
    return r;
}
__device__ __forceinline__ void lds_v2u64(uint64_t& a, uint64_t& b, uint32_t off) {
    asm("ld.shared.v2.u64 {%0, %1}, [%2];" : "=l"(a), "=l"(b) : "r"(off));
}

// ---------- zero kernel (stream B, before edge) ----------
__global__ void zero_kernel() {
    int i = blockIdx.x * blockDim.x + threadIdx.x;
    if (i < N_NODES) { g_deg[i] = 0.f; g_sw[i] = 0.f; }
}

// ---------- edge kernel: 4 edges/thread ----------
__global__ void edge_kernel(const int* __restrict__ ei,
                            const float* __restrict__ ew) {
    int t4 = blockIdx.x * blockDim.x + threadIdx.x;
    if (t4 < NE / 4) {
        int4   v4 = *(const int4*)(ei + NE + 4 * t4);   // edge_index row 1
        float4 w4 = *(const float4*)(ew + 4 * t4);
        if ((unsigned)v4.x < N_NODES) { atomicAdd(&g_deg[v4.x], 1.0f); atomicAdd(&g_sw[v4.x], w4.x); }
        if ((unsigned)v4.y < N_NODES) { atomicAdd(&g_deg[v4.y], 1.0f); atomicAdd(&g_sw[v4.y], w4.y); }
        if ((unsigned)v4.z < N_NODES) { atomicAdd(&g_deg[v4.z], 1.0f); atomicAdd(&g_sw[v4.z], w4.z); }
        if ((unsigned)v4.w < N_NODES) { atomicAdd(&g_deg[v4.w], 1.0f); atomicAdd(&g_sw[v4.w], w4.w); }
    }
}

// ---------- trans kernel (main stream): transMu + c3 + transW ----------
__global__ void __launch_bounds__(256)
trans_kernel(const float* __restrict__ mu, const float* __restrict__ W2,
             const float* __restrict__ W7, const float* __restrict__ W3,
             const float* __restrict__ W4) {
    __shared__ float S[64][65];
    int b = blockIdx.x;
    int tid = threadIdx.x;

    if (b < 782) {                       // transMu (64-row tiles)
        int v0 = b * 64;
#pragma unroll
        for (int s = 0; s < 16; s++) {
            int j = tid + 256 * s;
            int r = j >> 6, k = j & 63;
            int v = v0 + r;
            S[r][k] = (v < N_NODES) ? mu[v * 64 + k] : 0.f;
        }
        __syncthreads();
#pragma unroll
        for (int s = 0; s < 16; s++) {
            int j = tid + 256 * s;
            int k = j >> 6, r = j & 63;
            g_muT[k][v0 + r] = S[r][k];
        }
    } else if (b == 782) {               // c3 + zero g_S
        int t = tid >> 6, h = tid & 63;
        S[t][h] = fmaxf(W4[t * HD + h], 0.f);
        if (tid < 64) g_S[tid] = 0.f;
        __syncthreads();
        float s = 0.f;
        const float* row = W3 + t * HD * HD + h * HD;
#pragma unroll 16
        for (int k = 0; k < HD; k++) s = fmaf(row[k], S[t][k], s);
        g_c3[t * HD + h] = s;
    } else {                             // transW, layers 0..4
        int l = b - 783;
        const float* src = (l < 4) ? (W2 + l * 4096) : W7;
#pragma unroll
        for (int s = 0; s < 16; s++) {
            int j = tid + 256 * s;
            S[j >> 6][j & 63] = src[j];
        }
        __syncthreads();
#pragma unroll
        for (int s = 0; s < 16; s++) {
            int j = tid + 256 * s;
            g_WT[l][j >> 6][j & 63] = S[j & 63][j >> 6];
        }
    }
}

// ---------- fused kernel: 4 S2V steps + readout; 128-node tile, 256 threads ----------
// Thread tile: 4 cols (c0=4*(tid>>4)) x 8 rows ({4qy..+3} U {64+4qy..+3}).
// muT loaded as v2.u64 (pre-packed FFMA2 operands); weights float4 + splat.
__global__ void __launch_bounds__(256, 4)
fused_kernel(const float* __restrict__ x,
             const float* __restrict__ W1,
             const float* __restrict__ W5,
             float* __restrict__ out) {
    __shared__ __align__(16) float Ws[HD][WSTRIDE];
    __shared__ __align__(16) float muT[HD][RSTRIDE];
    __shared__ float xs[128], degs[128], sws[128];
    __shared__ float w1s[64], c3s[64];
    __shared__ float colp[4][64];

    float (*red)[17] = (float (*)[17])&muT[0][0];   // alias (muT dead at use)

    const int tid = threadIdx.x;
    const int cx = tid >> 4;       // 0..15
    const int qy = tid & 15;       // 0..15
    const int c0 = cx * 4;
    const int rA = qy * 4;
    const int rB = 64 + qy * 4;
    const int v0 = blockIdx.x * 128;

    const uint32_t mu_base  = sptr(&muT[0][0]);
    const uint32_t moffA0   = mu_base + rA * 4;
    const uint32_t moffB0   = mu_base + rB * 4;
    const uint32_t mrow     = RSTRIDE * 4;

    // stage mu tile: straight float4 copies
#pragma unroll
    for (int s = 0; s < 8; s++) {
        int j = tid + 256 * s;
        int k = j >> 5, q = j & 31;
        *(float4*)&muT[k][4 * q] = *(const float4*)&g_muT[k][v0 + 4 * q];
    }
    if (tid < 128) {
        int v = v0 + tid;
        xs[tid]   = (v < N_NODES) ? x[v]     : 0.f;
        degs[tid] = (v < N_NODES) ? g_deg[v] : 0.f;
        sws[tid]  = (v < N_NODES) ? g_sw[v]  : 0.f;
    }

#pragma unroll 1
    for (int t = 0; t < TSTEPS; t++) {
        __syncthreads();
#pragma unroll
        for (int s = 0; s < 4; s++) {
            int j = tid + 256 * s;
            int k = j >> 4, q = j & 15;
            *(float4*)&Ws[k][4 * q] = *(const float4*)&g_WT[t][k][4 * q];
        }
        if (tid < 64) { w1s[tid] = W1[t * 64 + tid]; c3s[tid] = g_c3[t * 64 + tid]; }
        __syncthreads();

        uint64_t acc[4][4];   // [col i][pair: rA01,rA23,rB01,rB23]
#pragma unroll
        for (int i = 0; i < 4; i++)
#pragma unroll
            for (int p = 0; p < 4; p++) acc[i][p] = 0ULL;

        uint32_t moffA = moffA0, moffB = moffB0;
#pragma unroll 8
        for (int k = 0; k < 64; k++) {
            uint64_t a01, a23, b01, b23;
            lds_v2u64(a01, a23, moffA);
            lds_v2u64(b01, b23, moffB);
            moffA += mrow; moffB += mrow;
            float4 w = *(const float4*)&Ws[k][c0];   // broadcast (2 addrs/warp)
            uint64_t wp;
            wp = splat2(w.x);
            ffma2(acc[0][0], a01, wp); ffma2(acc[0][1], a23, wp);
            ffma2(acc[0][2], b01, wp); ffma2(acc[0][3], b23, wp);
            wp = splat2(w.y);
            ffma2(acc[1][0], a01, wp); ffma2(acc[1][1], a23, wp);
            ffma2(acc[1][2], b01, wp); ffma2(acc[1][3], b23, wp);
            wp = splat2(w.z);
            ffma2(acc[2][0], a01, wp); ffma2(acc[2][1], a23, wp);
            ffma2(acc[2][2], b01, wp); ffma2(acc[2][3], b23, wp);
            wp = splat2(w.w);
            ffma2(acc[3][0], a01, wp); ffma2(acc[3][1], a23, wp);
            ffma2(acc[3][2], b01, wp); ffma2(acc[3][3], b23, wp);
        }
        __syncthreads();

        // epilogue: mu' = relu(x*w1 + deg*acc + sw*c3)
#pragma unroll
        for (int i = 0; i < 4; i++) {
            int c = c0 + i;
            float w1c = w1s[c], c3c = c3s[c];
            float2 p0 = unpack2(acc[i][0]);
            float2 p1 = unpack2(acc[i][1]);
            float4 o;
            o.x = fmaxf(fmaf(xs[rA+0], w1c, fmaf(degs[rA+0], p0.x, sws[rA+0] * c3c)), 0.f);
            o.y = fmaxf(fmaf(xs[rA+1], w1c, fmaf(degs[rA+1], p0.y, sws[rA+1] * c3c)), 0.f);
            o.z = fmaxf(fmaf(xs[rA+2], w1c, fmaf(degs[rA+2], p1.x, sws[rA+2] * c3c)), 0.f);
            o.w = fmaxf(fmaf(xs[rA+3], w1c, fmaf(degs[rA+3], p1.y, sws[rA+3] * c3c)), 0.f);
            *(float4*)&muT[c][rA] = o;
            float2 p2 = unpack2(acc[i][2]);
            float2 p3 = unpack2(acc[i][3]);
            o.x = fmaxf(fmaf(xs[rB+0], w1c, fmaf(degs[rB+0], p2.x, sws[rB+0] * c3c)), 0.f);
            o.y = fmaxf(fmaf(xs[rB+1], w1c, fmaf(degs[rB+1], p2.y, sws[rB+1] * c3c)), 0.f);
            o.z = fmaxf(fmaf(xs[rB+2], w1c, fmaf(degs[rB+2], p3.x, sws[rB+2] * c3c)), 0.f);
            o.w = fmaxf(fmaf(xs[rB+3], w1c, fmaf(degs[rB+3], p3.y, sws[rB+3] * c3c)), 0.f);
            *(float4*)&muT[c][rB] = o;
        }
    }
    __syncthreads();

    // graph-pool column partials over 128 rows
    {
        int h = tid & 63, g = tid >> 6;
        float s = 0.f;
#pragma unroll
        for (int j = 0; j < 32; j++) s += muT[h][g * 32 + j];
        colp[g][h] = s;
    }
    // stage W7^T and W5 node-half
#pragma unroll
    for (int s = 0; s < 4; s++) {
        int j = tid + 256 * s;
        int k = j >> 4, q = j & 15;
        *(float4*)&Ws[k][4 * q] = *(const float4*)&g_WT[4][k][4 * q];
    }
    if (tid < 64) w1s[tid] = W5[64 + tid];
    __syncthreads();

    if (tid < 64)
        atomicAdd(&g_S[tid], colp[0][tid] + colp[1][tid] + colp[2][tid] + colp[3][tid]);

    // final GEMM: nodes_vec = mu @ W7^T
    uint64_t acc[4][4];
#pragma unroll
    for (int i = 0; i < 4; i++)
#pragma unroll
        for (int p = 0; p < 4; p++) acc[i][p] = 0ULL;

    uint32_t moffA = moffA0, moffB = moffB0;
#pragma unroll 8
    for (int k = 0; k < 64; k++) {
        uint64_t a01, a23, b01, b23;
        lds_v2u64(a01, a23, moffA);
        lds_v2u64(b01, b23, moffB);
        moffA += mrow; moffB += mrow;
        float4 w = *(const float4*)&Ws[k][c0];
        uint64_t wp;
        wp = splat2(w.x);
        ffma2(acc[0][0], a01, wp); ffma2(acc[0][1], a23, wp);
        ffma2(acc[0][2], b01, wp); ffma2(acc[0][3], b23, wp);
        wp = splat2(w.y);
        ffma2(acc[1][0], a01, wp); ffma2(acc[1][1], a23, wp);
        ffma2(acc[1][2], b01, wp); ffma2(acc[1][3], b23, wp);
        wp = splat2(w.z);
        ffma2(acc[2][0], a01, wp); ffma2(acc[2][1], a23, wp);
        ffma2(acc[2][2], b01, wp); ffma2(acc[2][3], b23, wp);
        wp = splat2(w.w);
        ffma2(acc[3][0], a01, wp); ffma2(acc[3][1], a23, wp);
        ffma2(acc[3][2], b01, wp); ffma2(acc[3][3], b23, wp);
    }

    float prA[4] = {0.f, 0.f, 0.f, 0.f};
    float prB[4] = {0.f, 0.f, 0.f, 0.f};
#pragma unroll
    for (int i = 0; i < 4; i++) {
        float wb = w1s[c0 + i];
        float2 p0 = unpack2(acc[i][0]);
        float2 p1 = unpack2(acc[i][1]);
        float2 p2 = unpack2(acc[i][2]);
        float2 p3 = unpack2(acc[i][3]);
        prA[0] = fmaf(fmaxf(p0.x, 0.f), wb, prA[0]);
        prA[1] = fmaf(fmaxf(p0.y, 0.f), wb, prA[1]);
        prA[2] = fmaf(fmaxf(p1.x, 0.f), wb, prA[2]);
        prA[3] = fmaf(fmaxf(p1.y, 0.f), wb, prA[3]);
        prB[0] = fmaf(fmaxf(p2.x, 0.f), wb, prB[0]);
        prB[1] = fmaf(fmaxf(p2.y, 0.f), wb, prB[1]);
        prB[2] = fmaf(fmaxf(p3.x, 0.f), wb, prB[2]);
        prB[3] = fmaf(fmaxf(p3.y, 0.f), wb, prB[3]);
    }
    __syncthreads();
#pragma unroll
    for (int j = 0; j < 4; j++) {
        red[rA + j][cx] = prA[j];
        red[rB + j][cx] = prB[j];
    }
    __syncthreads();

    if (tid < 128) {
        float s = 0.f;
#pragma unroll
        for (int q = 0; q < 16; q++) s += red[tid][q];
        int v = v0 + tid;
        if (v < N_NODES) out[v] = s;
    }
}

// graph-pool scalar + broadcast add
__global__ void add_kernel(const float* __restrict__ W5, float* __restrict__ out) {
    __shared__ float sh[64];
    __shared__ float cval;
    int tid = threadIdx.x;
    if (tid < 64) sh[tid] = fmaxf(g_S[tid], 0.f) * W5[tid];
    __syncthreads();
    if (tid == 0) {
        float s = 0.f;
#pragma unroll
        for (int i = 0; i < 64; i++) s += sh[i];
        cval = s;
    }
    __syncthreads();
    int v = blockIdx.x * blockDim.x + tid;
    if (v < N_NODES) out[v] += cval;
}

// ---------- launch (fork-join: [zero->edge] || [trans], then fused, add) ----------
extern "C" void kernel_launch(void* const* d_in, const int* in_sizes, int n_in,
                              void* d_out, int out_size) {
    const float* mu = (const float*)d_in[0];
    const float* x  = (const float*)d_in[1];
    const int*   ei = (const int*)d_in[2];     // int32 (JAX x64 disabled)
    const float* ew = (const float*)d_in[3];
    const float* W1 = (const float*)d_in[4];
    const float* W2 = (const float*)d_in[5];
    const float* W3 = (const float*)d_in[6];
    const float* W4 = (const float*)d_in[7];
    const float* W5 = (const float*)d_in[8];
    const float* W7 = (const float*)d_in[9];
    float* out = (float*)d_out;

    cudaStream_t s1;
    cudaEvent_t ev0, ev1;
    cudaStreamCreateWithFlags(&s1, cudaStreamNonBlocking);
    cudaEventCreateWithFlags(&ev0, cudaEventDisableTiming);
    cudaEventCreateWithFlags(&ev1, cudaEventDisableTiming);

    // fork: side stream does zero -> edge
    cudaEventRecord(ev0, 0);
    cudaStreamWaitEvent(s1, ev0, 0);
    zero_kernel<<<(N_NODES + 255) / 256, 256, 0, s1>>>();
    edge_kernel<<<(NE / 4 + 255) / 256, 256, 0, s1>>>(ei, ew);
    cudaEventRecord(ev1, s1);

    // main stream does transposes concurrently
    trans_kernel<<<788, 256>>>(mu, W2, W7, W3, W4);

    // join, then fused + add on main stream
    cudaStreamWaitEvent(0, ev1, 0);
    fused_kernel<<<NPAD / 128, 256>>>(x, W1, W5, out);
    add_kernel<<<(N_NODES + 255) / 256, 256>>>(W5, out);
}